// round 15
// baseline (speedup 1.0000x reference)
#include <cuda_runtime.h>
#include <cuda_fp16.h>
#include <cstdint>

typedef unsigned int u32;

#define NN 45056
#define EE 720896
#define FEA 60
#define HID 256
#define MACH 22
#define BATCH 2048
#define CAP 96
#define MLP_IN 6952
#define KP0 6960
#define KP1 64
#define NEG_SLOPE 0.01f

// ---------------- fp32 scratch ----------------------------------------------
static constexpr size_t ZSZ  = (size_t)BATCH * HID;
static constexpr size_t OFF_DINV = 0;
static constexpr size_t OFF_ZP   = OFF_DINV + (size_t)NN;
static constexpr size_t FTOTAL   = OFF_ZP   + 8 * ZSZ;
__device__ float g_f[FTOTAL];

// ---------------- packed adjacency: (src, weight-bits) per slot --------------
__device__ __align__(16) int2 g_srcw[(size_t)NN * CAP];
__device__ int g_cnt[NN];
__device__ int g_is32;

// ---------------- fp16 scratch ------------------------------------------------
static constexpr size_t XSZ  = (size_t)NN * KP1;
static constexpr size_t HSZ  = (size_t)NN * HID;
static constexpr size_t FSZ  = (size_t)BATCH * KP0;
static constexpr size_t W1SZ = (size_t)KP1 * HID;
static constexpr size_t W2SZ = (size_t)HID * HID;
static constexpr size_t F0SZ = (size_t)KP0 * HID;
static constexpr size_t OFF_XP  = 0;
static constexpr size_t OFF_XQ  = OFF_XP + XSZ;
static constexpr size_t OFF_H   = OFF_XQ + XSZ;
static constexpr size_t OFF_A   = OFF_H  + HSZ;
static constexpr size_t OFF_F   = OFF_A  + HSZ;
static constexpr size_t OFF_W1  = OFF_F  + FSZ;
static constexpr size_t OFF_W2  = OFF_W1 + W1SZ;
static constexpr size_t OFF_F0  = OFF_W2 + W2SZ;
static constexpr size_t OFF_F1  = OFF_F0 + F0SZ;
static constexpr size_t OFF_F2  = OFF_F1 + W2SZ;
static constexpr size_t OFF_Z   = OFF_F2 + W2SZ;
static constexpr size_t HTOTAL  = OFF_Z  + ZSZ;
__device__ __align__(16) __half g_h[HTOTAL];

// ---------------- helpers ----------------------------------------------------
__device__ __forceinline__ u32 smem_u32(const void* p) {
    return (u32)__cvta_generic_to_shared(p);
}
__device__ __forceinline__ void cp16(u32 dst, const void* src) {
    asm volatile("cp.async.cg.shared.global [%0], [%1], 16;" :: "r"(dst), "l"(src));
}
__device__ __forceinline__ void ldsm_x4(u32* r, u32 a) {
    asm volatile("ldmatrix.sync.aligned.m8n8.x4.shared.b16 {%0,%1,%2,%3}, [%4];"
        : "=r"(r[0]), "=r"(r[1]), "=r"(r[2]), "=r"(r[3]) : "r"(a));
}
__device__ __forceinline__ void ldsm_x4_t(u32* r, u32 a) {
    asm volatile("ldmatrix.sync.aligned.m8n8.x4.trans.shared.b16 {%0,%1,%2,%3}, [%4];"
        : "=r"(r[0]), "=r"(r[1]), "=r"(r[2]), "=r"(r[3]) : "r"(a));
}
__device__ __forceinline__ void mmaf16(float* c, const u32* a, const u32* b) {
    asm volatile(
        "mma.sync.aligned.m16n8k16.row.col.f32.f16.f16.f32 "
        "{%0,%1,%2,%3}, {%4,%5,%6,%7}, {%8,%9}, {%0,%1,%2,%3};"
        : "+f"(c[0]), "+f"(c[1]), "+f"(c[2]), "+f"(c[3])
        : "r"(a[0]), "r"(a[1]), "r"(a[2]), "r"(a[3]), "r"(b[0]), "r"(b[1]));
}
__device__ __forceinline__ void h8_acc(uint4 v, float w, float* acc) {
    float2 p;
    p = __half22float2(*(__half2*)&v.x); acc[0] = fmaf(w, p.x, acc[0]); acc[1] = fmaf(w, p.y, acc[1]);
    p = __half22float2(*(__half2*)&v.y); acc[2] = fmaf(w, p.x, acc[2]); acc[3] = fmaf(w, p.y, acc[3]);
    p = __half22float2(*(__half2*)&v.z); acc[4] = fmaf(w, p.x, acc[4]); acc[5] = fmaf(w, p.y, acc[5]);
    p = __half22float2(*(__half2*)&v.w); acc[6] = fmaf(w, p.x, acc[6]); acc[7] = fmaf(w, p.y, acc[7]);
}
__device__ __forceinline__ void h8_scale(uint4 v, float s, float* acc) {
    float2 p;
    p = __half22float2(*(__half2*)&v.x); acc[0] = s * p.x; acc[1] = s * p.y;
    p = __half22float2(*(__half2*)&v.y); acc[2] = s * p.x; acc[3] = s * p.y;
    p = __half22float2(*(__half2*)&v.z); acc[4] = s * p.x; acc[5] = s * p.y;
    p = __half22float2(*(__half2*)&v.w); acc[6] = s * p.x; acc[7] = s * p.y;
}
__device__ __forceinline__ uint4 f8_to_h8(const float* f) {
    uint4 o;
    *(__half2*)&o.x = __floats2half2_rn(f[0], f[1]);
    *(__half2*)&o.y = __floats2half2_rn(f[2], f[3]);
    *(__half2*)&o.z = __floats2half2_rn(f[4], f[5]);
    *(__half2*)&o.w = __floats2half2_rn(f[6], f[7]);
    return o;
}

// ---------------- merged prep: dtype detect + cnt zero + x pad + weights + flat-x
#define XB   ((int)(XSZ / 256))                     // 11264 blocks: x->fp16 pad + cnt
#define CVTB 7792                                   // weight conversion blocks
#define NNFEA ((long long)NN * FEA)
#define XPADB 10624                                 // (NNFEA + BATCH*8)/256
__global__ void k_prep(const void* __restrict__ ei, const float* __restrict__ x,
                       const float* __restrict__ W1, const float* __restrict__ W2,
                       const float* __restrict__ Wf0, const float* __restrict__ Wf1,
                       const float* __restrict__ Wf2,
                       int* __restrict__ cnt, __half* __restrict__ gh_base) {
    int blk = blockIdx.x;
    int t = threadIdx.x;
    if (blk < XB) {
        size_t idx = (size_t)blk * 256 + t;
        int i = (int)(idx >> 6), k = (int)(idx & 63);
        gh_base[OFF_XP + idx] = __float2half((k < FEA) ? x[(size_t)i * FEA + k] : 0.f);
        if (idx < NN) cnt[idx] = 0;
        if (idx == 0) {
            const long long* p = (const long long*)ei;
            int is32 = 0;
            for (int q = 0; q < 64; q++) {
                long long v = p[q];
                if (v < 0 || v >= NN) { is32 = 1; break; }
            }
            g_is32 = is32;
        }
        return;
    }
    blk -= XB;
    if (blk < CVTB) {
        int r = blk;
        float v; size_t off;
        __half* d;
        if (r < 64) {
            v = (r < FEA) ? W1[(size_t)r * 256 + t] : 0.f;
            d = gh_base + OFF_W1; off = (size_t)r * 256 + t;
        } else if (r < 320) {
            int k = r - 64;
            v = W2[(size_t)k * 256 + t];
            d = gh_base + OFF_W2; off = (size_t)k * 256 + t;
        } else if (r < 7280) {
            int k = r - 320;
            v = (k < MLP_IN) ? Wf0[(size_t)k * 256 + t] : 0.f;
            d = gh_base + OFF_F0; off = (size_t)k * 256 + t;
        } else if (r < 7536) {
            int k = r - 7280;
            v = Wf1[(size_t)k * 256 + t];
            d = gh_base + OFF_F1; off = (size_t)k * 256 + t;
        } else {
            int k = r - 7536;
            v = Wf2[(size_t)k * 256 + t];
            d = gh_base + OFF_F2; off = (size_t)k * 256 + t;
        }
        d[off] = __float2half(v);
        return;
    }
    blk -= CVTB;
    {
        __half* f = gh_base + OFF_F;
        long long idx = (long long)blk * 256 + t;
        if (idx < NNFEA) {
            int i = (int)(idx / FEA);
            int j = (int)(idx - (long long)i * FEA);
            int b = i / MACH, m = i - b * MACH;
            f[(size_t)b * KP0 + (size_t)m * (HID + FEA) + HID + j] = __float2half(x[idx]);
        } else {
            long long q = idx - NNFEA;
            int b = (int)(q >> 3), j = (int)(q & 7);
            f[(size_t)b * KP0 + MLP_IN + j] = __float2half(0.f);
        }
    }
}

__device__ __forceinline__ int edge_idx(const void* ei, int half, int e, int is32) {
    if (is32) return ((const int*)ei)[(size_t)half * EE + e];
    return (int)((const long long*)ei)[(size_t)half * EE + e];
}
__global__ void k_degfill(const void* __restrict__ ei, const float* __restrict__ ew,
                          int* __restrict__ cnt, int2* __restrict__ srcw) {
    int e = blockIdx.x * 256 + threadIdx.x;
    if (e >= EE) return;
    int is32 = g_is32;
    int r = edge_idx(ei, 0, e, is32);
    int c = edge_idx(ei, 1, e, is32);
    if ((unsigned)r >= (unsigned)NN || (unsigned)c >= (unsigned)NN) return;
    float w = ew[e];
    int p = atomicAdd(&cnt[c], 1);
    if (p < CAP) srcw[(size_t)c * CAP + p] = make_int2(r, __float_as_int(w));
}
__global__ void k_dinv(const int2* __restrict__ srcw, const int* __restrict__ cnt,
                       float* __restrict__ dinv) {
    int node = (blockIdx.x * 256 + threadIdx.x) >> 5;
    int lane = threadIdx.x & 31;
    if (node >= NN) return;
    int c = cnt[node]; if (c > CAP) c = CAP;
    float s = 0.f;
    for (int e = lane; e < c; e += 32) s += __int_as_float(srcw[(size_t)node * CAP + e].y);
#pragma unroll
    for (int o = 16; o; o >>= 1) s += __shfl_xor_sync(0xffffffffu, s, o);
    if (lane == 0) dinv[node] = rsqrtf(s + 1.0f);
}

// ---------------- gather x (fp16 uint4, 8 lanes/node, 4-wide batched) --------
__global__ __launch_bounds__(256)
void k_gather_x(const uint4* __restrict__ xp4, const float* __restrict__ dinv,
                const int* __restrict__ cnt, const int2* __restrict__ srcw,
                uint4* __restrict__ xq4) {
    int sub = threadIdx.x >> 3, lane = threadIdx.x & 7;
    int i = blockIdx.x * 32 + sub;
    __shared__ int   ssrc[32][CAP];
    __shared__ float snrm[32][CAP];
    int c = cnt[i]; if (c > CAP) c = CAP;
    float di = dinv[i];
    for (int e = lane; e < c; e += 8) {
        int2 sv = srcw[(size_t)i * CAP + e];
        ssrc[sub][e] = sv.x * 8;
        snrm[sub][e] = dinv[sv.x] * __int_as_float(sv.y) * di;
    }
    __syncwarp();

    float acc[8];
    h8_scale(xp4[i * 8 + lane], di * di, acc);
    int e = 0;
    for (; e + 4 <= c; e += 4) {
        uint4 v0 = xp4[ssrc[sub][e]     + lane];
        uint4 v1 = xp4[ssrc[sub][e + 1] + lane];
        uint4 v2 = xp4[ssrc[sub][e + 2] + lane];
        uint4 v3 = xp4[ssrc[sub][e + 3] + lane];
        h8_acc(v0, snrm[sub][e],     acc);
        h8_acc(v1, snrm[sub][e + 1], acc);
        h8_acc(v2, snrm[sub][e + 2], acc);
        h8_acc(v3, snrm[sub][e + 3], acc);
    }
    for (; e < c; e++)
        h8_acc(xp4[ssrc[sub][e] + lane], snrm[sub][e], acc);
    xq4[i * 8 + lane] = f8_to_h8(acc);
}

// ---------------- gather h (fp16 uint4, 1 warp/node, 4-wide batched) ---------
__global__ __launch_bounds__(256)
void k_gather_h(const uint4* __restrict__ h4,
                const float* __restrict__ dinv, const int* __restrict__ cnt,
                const int2* __restrict__ srcw, uint4* __restrict__ a4) {
    int sub = threadIdx.x >> 5, lane = threadIdx.x & 31;
    int i = blockIdx.x * 8 + sub;
    __shared__ int   ssrc[8][CAP];
    __shared__ float snrm[8][CAP];
    int c = cnt[i]; if (c > CAP) c = CAP;
    float di = dinv[i];
    for (int e = lane; e < c; e += 32) {
        int2 sv = srcw[(size_t)i * CAP + e];
        ssrc[sub][e] = sv.x * 32;
        snrm[sub][e] = dinv[sv.x] * __int_as_float(sv.y) * di;
    }
    __syncwarp();

    float acc[8];
    h8_scale(h4[i * 32 + lane], di * di, acc);
    int e = 0;
    for (; e + 4 <= c; e += 4) {
        uint4 v0 = h4[ssrc[sub][e]     + lane];
        uint4 v1 = h4[ssrc[sub][e + 1] + lane];
        uint4 v2 = h4[ssrc[sub][e + 2] + lane];
        uint4 v3 = h4[ssrc[sub][e + 3] + lane];
        h8_acc(v0, snrm[sub][e],     acc);
        h8_acc(v1, snrm[sub][e + 1], acc);
        h8_acc(v2, snrm[sub][e + 2], acc);
        h8_acc(v3, snrm[sub][e + 3], acc);
    }
    for (; e < c; e++)
        h8_acc(h4[ssrc[sub][e] + lane], snrm[sub][e], acc);
    a4[i * 32 + lane] = f8_to_h8(acc);
}

// ---------------- fp16 tensor-core GEMM (cp.async 3-stage pipeline) ----------
// MODE 0: fp32 partial store to C + blockIdx.z*ZSZ (split-K)
// MODE 1: bias + leaky + fp16 store, linear stride 256 (conv1 -> h)
// MODE 2: bias + leaky + fp16 store, flat-mapped (conv2 -> flat)
template<int MODE>
__global__ __launch_bounds__(256)
void bmma(const __half* __restrict__ A, const __half* __restrict__ B,
          float* __restrict__ C, const float* __restrict__ bias,
          __half* __restrict__ o, int K, int kstep) {
    __shared__ __align__(16) __half As[3][128][24];
    __shared__ __align__(16) __half Bs[3][16][136];
    constexpr u32 ABUF = 128 * 24 * 2;
    constexpr u32 BBUF = 16 * 136 * 2;

    const int tid = threadIdx.x;
    const int lane = tid & 31, warp = tid >> 5;
    const int wm = warp >> 2, wn = warp & 3;
    const int row0 = blockIdx.y * 128, col0 = blockIdx.x * 128;
    const int kb = blockIdx.z * kstep;
    const int ke = min(kb + kstep, K);

    const int ar = tid >> 1, ac = (tid & 1) * 8;
    const int bkr = tid >> 4, bc = (tid & 15) * 8;
    const size_t a_base = (size_t)(row0 + ar) * K + ac;

    const u32 a_dst = smem_u32(&As[0][ar][ac]);
    const u32 b_dst = smem_u32(&Bs[0][bkr][bc]);

    float acc[4][4][4];
#pragma unroll
    for (int i = 0; i < 4; i++)
#pragma unroll
        for (int j = 0; j < 4; j++)
#pragma unroll
            for (int q = 0; q < 4; q++) acc[i][j][q] = 0.f;

    const int lr = (lane & 7) + ((lane >> 3) & 1) * 8;
    const int lc = (lane >> 4) * 8;
    u32 aaddr[4], baddr[2];
#pragma unroll
    for (int mf = 0; mf < 4; mf++)
        aaddr[mf] = smem_u32(&As[0][wm * 64 + mf * 16 + lr][lc]);
#pragma unroll
    for (int g = 0; g < 2; g++)
        baddr[g] = smem_u32(&Bs[0][lr][wn * 32 + g * 16 + lc]);

    auto load_stage = [&](int buf, int k0) {
        if (k0 < ke) {
            cp16(a_dst + buf * ABUF, A + a_base + k0);
            cp16(b_dst + buf * BBUF, B + (size_t)(k0 + bkr) * 256 + col0 + bc);
        }
        asm volatile("cp.async.commit_group;");
    };

    load_stage(0, kb);
    load_stage(1, kb + 16);
    load_stage(2, kb + 32);

    int buf = 0;
    for (int k0 = kb; k0 < ke; k0 += 16) {
        asm volatile("cp.async.wait_group 2;");
        __syncthreads();

        u32 a[4][4], b[4][2];
#pragma unroll
        for (int mf = 0; mf < 4; mf++)
            ldsm_x4(a[mf], aaddr[mf] + buf * ABUF);
#pragma unroll
        for (int g = 0; g < 2; g++) {
            u32 t[4];
            ldsm_x4_t(t, baddr[g] + buf * BBUF);
            b[2*g][0] = t[0]; b[2*g][1] = t[1];
            b[2*g+1][0] = t[2]; b[2*g+1][1] = t[3];
        }
#pragma unroll
        for (int mf = 0; mf < 4; mf++)
#pragma unroll
            for (int nf = 0; nf < 4; nf++)
                mmaf16(acc[mf][nf], a[mf], b[nf]);
        __syncthreads();
        load_stage(buf, k0 + 48);
        buf = (buf == 2) ? 0 : buf + 1;
    }

    const int er = lane >> 2, ec = (lane & 3) * 2;
    float* Cz = (MODE == 0) ? C + (size_t)blockIdx.z * ZSZ : C;
#pragma unroll
    for (int mf = 0; mf < 4; mf++)
#pragma unroll
        for (int nf = 0; nf < 4; nf++) {
            int r = row0 + wm * 64 + mf * 16 + er;
            int c = col0 + wn * 32 + nf * 8 + ec;
            if (MODE == 0) {
                float* p0 = &Cz[(size_t)r * 256 + c];
                float* p1 = &Cz[(size_t)(r + 8) * 256 + c];
                p0[0] = acc[mf][nf][0]; p0[1] = acc[mf][nf][1];
                p1[0] = acc[mf][nf][2]; p1[1] = acc[mf][nf][3];
            } else {
                float bv0 = bias[c], bv1 = bias[c + 1];
#pragma unroll
                for (int half = 0; half < 2; half++) {
                    int rr = r + half * 8;
                    float v0 = acc[mf][nf][half * 2]     + bv0;
                    float v1 = acc[mf][nf][half * 2 + 1] + bv1;
                    v0 = v0 > 0.f ? v0 : NEG_SLOPE * v0;
                    v1 = v1 > 0.f ? v1 : NEG_SLOPE * v1;
                    size_t p;
                    if (MODE == 1) {
                        p = (size_t)rr * 256 + c;
                    } else {
                        int b = rr / MACH, m = rr - b * MACH;
                        p = (size_t)b * KP0 + (size_t)m * (HID + FEA) + c;
                    }
                    *(__half2*)&o[p] = __floats2half2_rn(v0, v1);
                }
            }
        }
}

// ---------------- split-K reduce + bias + leaky + fp16 store (float4 loads) --
template<int S>
__global__ void k_epi(const float* __restrict__ zp, const float* __restrict__ bias,
                      __half* __restrict__ z) {
    size_t i4 = (size_t)blockIdx.x * 256 + threadIdx.x;   // index in float4 units
    int cbase = (int)((i4 & 63) << 2);
    float4 v = *(const float4*)&zp[i4 * 4];
#pragma unroll
    for (int s = 1; s < S; s++) {
        float4 u = *(const float4*)&zp[s * ZSZ + i4 * 4];
        v.x += u.x; v.y += u.y; v.z += u.z; v.w += u.w;
    }
    v.x += bias[cbase + 0]; v.y += bias[cbase + 1];
    v.z += bias[cbase + 2]; v.w += bias[cbase + 3];
    v.x = v.x > 0.f ? v.x : NEG_SLOPE * v.x;
    v.y = v.y > 0.f ? v.y : NEG_SLOPE * v.y;
    v.z = v.z > 0.f ? v.z : NEG_SLOPE * v.z;
    v.w = v.w > 0.f ? v.w : NEG_SLOPE * v.w;
    uint2 o;
    *(__half2*)&o.x = __floats2half2_rn(v.x, v.y);
    *(__half2*)&o.y = __floats2half2_rn(v.z, v.w);
    *(uint2*)&z[i4 * 4] = o;
}

// ---------------- final: reduce + bias + leaky + head GEMV -------------------
__global__ __launch_bounds__(256)
void k_epihead(const float* __restrict__ zp, const float* __restrict__ bias,
               const float* __restrict__ Wo, const float* __restrict__ bo,
               float* __restrict__ out) {
    __shared__ float zrow[HID];
    int b = blockIdx.x, t = threadIdx.x;
    size_t i = (size_t)b * HID + t;
    float v = bias[t];
#pragma unroll
    for (int s = 0; s < 4; s++) v += zp[s * ZSZ + i];
    v = v > 0.f ? v : NEG_SLOPE * v;
    zrow[t] = v;
    __syncthreads();
    if (t < 128) {
        int j = t >> 5, lane = t & 31;
        float a = 0.f;
#pragma unroll
        for (int q = 0; q < 8; q++) {
            int k = lane + q * 32;
            a = fmaf(zrow[k], Wo[k * 4 + j], a);
        }
#pragma unroll
        for (int o = 16; o > 0; o >>= 1)
            a += __shfl_down_sync(0xffffffffu, a, o);
        if (lane == 0) out[(size_t)b * 4 + j] = a + bo[j];
    }
}

// ---------------- launcher ---------------------------------------------------
extern "C" void kernel_launch(void* const* d_in, const int* in_sizes, int n_in,
                              void* d_out, int out_size) {
    const float* x   = (const float*)d_in[0];
    const void*  ei  = d_in[1];
    const float* ew  = (const float*)d_in[2];
    const float* W1  = (const float*)d_in[3];
    const float* b1  = (const float*)d_in[4];
    const float* W2  = (const float*)d_in[5];
    const float* b2  = (const float*)d_in[6];
    const float* Wf0 = (const float*)d_in[7];
    const float* bf0 = (const float*)d_in[8];
    const float* Wf1 = (const float*)d_in[9];
    const float* bf1 = (const float*)d_in[10];
    const float* Wf2 = (const float*)d_in[11];
    const float* bf2 = (const float*)d_in[12];
    const float* Wo  = (const float*)d_in[13];
    const float* bo  = (const float*)d_in[14];
    float* out = (float*)d_out;

    float* gf = nullptr; int* gcnt = nullptr; int2* gsw = nullptr; __half* gh = nullptr;
    cudaGetSymbolAddress((void**)&gf, g_f);
    cudaGetSymbolAddress((void**)&gcnt, g_cnt);
    cudaGetSymbolAddress((void**)&gsw, g_srcw);
    cudaGetSymbolAddress((void**)&gh, g_h);

    float* dinv = gf + OFF_DINV;
    float* zp   = gf + OFF_ZP;

    __half *xp = gh + OFF_XP, *xq = gh + OFF_XQ;
    __half *h  = gh + OFF_H,  *a  = gh + OFF_A;
    __half *f  = gh + OFF_F;
    __half *w1 = gh + OFF_W1, *w2 = gh + OFF_W2;
    __half *f0 = gh + OFF_F0, *f1 = gh + OFF_F1, *f2 = gh + OFF_F2;
    __half *z  = gh + OFF_Z;

    const int NB_E = (EE + 255) / 256;

    // merged prep (x pad + cnt zero + dtype detect + weight cvt + flat-x)
    k_prep<<<XB + CVTB + XPADB, 256>>>(ei, x, W1, W2, Wf0, Wf1, Wf2, gcnt, gh);  // 1
    k_degfill<<<NB_E, 256>>>(ei, ew, gcnt, gsw);                                 // 2
    k_dinv<<<NN / 8, 256>>>(gsw, gcnt, dinv);                                    // 3
    k_gather_x<<<NN / 32, 256>>>((const uint4*)xp, dinv, gcnt, gsw,
                                 (uint4*)xq);                                    // 4 <- profiled

    // conv1
    bmma<1><<<dim3(2, NN / 128, 1), 256>>>(xq, w1, nullptr, b1, h, KP1, KP1);

    // conv2
    k_gather_h<<<NN / 8, 256>>>((const uint4*)h, dinv, gcnt, gsw, (uint4*)a);
    bmma<2><<<dim3(2, NN / 128, 1), 256>>>(a, w2, nullptr, b2, f, HID, HID);

    // MLP0: split-K=8 -> partials -> reduce epi (float4)
    bmma<0><<<dim3(2, BATCH / 128, 8), 256>>>(f, f0, zp, nullptr, nullptr, KP0, 880);
    k_epi<8><<<(int)(ZSZ / 1024), 256>>>(zp, bf0, z);

    // MLP1: split-K=4
    bmma<0><<<dim3(2, BATCH / 128, 4), 256>>>(z, f1, zp, nullptr, nullptr, HID, 64);
    k_epi<4><<<(int)(ZSZ / 1024), 256>>>(zp, bf1, z);

    // MLP2: split-K=4 -> fused reduce + head
    bmma<0><<<dim3(2, BATCH / 128, 4), 256>>>(z, f2, zp, nullptr, nullptr, HID, 64);
    k_epihead<<<BATCH, 256>>>(zp, bf2, Wo, bo, out);
}

// round 16
// speedup vs baseline: 1.0573x; 1.0573x over previous
#include <cuda_runtime.h>
#include <cuda_fp16.h>
#include <cstdint>

typedef unsigned int u32;

#define NN 45056
#define EE 720896
#define FEA 60
#define HID 256
#define MACH 22
#define BATCH 2048
#define CAP 96
#define MLP_IN 6952
#define KP0 6960
#define KP1 64
#define NEG_SLOPE 0.01f

// ---------------- fp32 scratch ----------------------------------------------
static constexpr size_t ZSZ  = (size_t)BATCH * HID;
static constexpr size_t OFF_DINV = 0;
static constexpr size_t OFF_ZP   = OFF_DINV + (size_t)NN;
static constexpr size_t FTOTAL   = OFF_ZP   + 8 * ZSZ;
__device__ float g_f[FTOTAL];

// ---------------- packed adjacency: (src, weight-bits) per slot --------------
__device__ __align__(16) int2 g_srcw[(size_t)NN * CAP];
__device__ int g_cnt[NN];
__device__ int g_is32;

// ---------------- fp16 scratch ------------------------------------------------
static constexpr size_t XSZ  = (size_t)NN * KP1;
static constexpr size_t HSZ  = (size_t)NN * HID;
static constexpr size_t FSZ  = (size_t)BATCH * KP0;
static constexpr size_t W1SZ = (size_t)KP1 * HID;
static constexpr size_t W2SZ = (size_t)HID * HID;
static constexpr size_t F0SZ = (size_t)KP0 * HID;
static constexpr size_t OFF_XP  = 0;
static constexpr size_t OFF_XQ  = OFF_XP + XSZ;
static constexpr size_t OFF_H   = OFF_XQ + XSZ;
static constexpr size_t OFF_A   = OFF_H  + HSZ;
static constexpr size_t OFF_F   = OFF_A  + HSZ;
static constexpr size_t OFF_W1  = OFF_F  + FSZ;
static constexpr size_t OFF_W2  = OFF_W1 + W1SZ;
static constexpr size_t OFF_F0  = OFF_W2 + W2SZ;
static constexpr size_t OFF_F1  = OFF_F0 + F0SZ;
static constexpr size_t OFF_F2  = OFF_F1 + W2SZ;
static constexpr size_t OFF_Z   = OFF_F2 + W2SZ;
static constexpr size_t HTOTAL  = OFF_Z  + ZSZ;
__device__ __align__(16) __half g_h[HTOTAL];

// ---------------- helpers ----------------------------------------------------
__device__ __forceinline__ u32 smem_u32(const void* p) {
    return (u32)__cvta_generic_to_shared(p);
}
__device__ __forceinline__ void cp16(u32 dst, const void* src) {
    asm volatile("cp.async.cg.shared.global [%0], [%1], 16;" :: "r"(dst), "l"(src));
}
__device__ __forceinline__ void ldsm_x4(u32* r, u32 a) {
    asm volatile("ldmatrix.sync.aligned.m8n8.x4.shared.b16 {%0,%1,%2,%3}, [%4];"
        : "=r"(r[0]), "=r"(r[1]), "=r"(r[2]), "=r"(r[3]) : "r"(a));
}
__device__ __forceinline__ void ldsm_x4_t(u32* r, u32 a) {
    asm volatile("ldmatrix.sync.aligned.m8n8.x4.trans.shared.b16 {%0,%1,%2,%3}, [%4];"
        : "=r"(r[0]), "=r"(r[1]), "=r"(r[2]), "=r"(r[3]) : "r"(a));
}
__device__ __forceinline__ void mmaf16(float* c, const u32* a, const u32* b) {
    asm volatile(
        "mma.sync.aligned.m16n8k16.row.col.f32.f16.f16.f32 "
        "{%0,%1,%2,%3}, {%4,%5,%6,%7}, {%8,%9}, {%0,%1,%2,%3};"
        : "+f"(c[0]), "+f"(c[1]), "+f"(c[2]), "+f"(c[3])
        : "r"(a[0]), "r"(a[1]), "r"(a[2]), "r"(a[3]), "r"(b[0]), "r"(b[1]));
}
__device__ __forceinline__ void h8_acc(uint4 v, float w, float* acc) {
    float2 p;
    p = __half22float2(*(__half2*)&v.x); acc[0] = fmaf(w, p.x, acc[0]); acc[1] = fmaf(w, p.y, acc[1]);
    p = __half22float2(*(__half2*)&v.y); acc[2] = fmaf(w, p.x, acc[2]); acc[3] = fmaf(w, p.y, acc[3]);
    p = __half22float2(*(__half2*)&v.z); acc[4] = fmaf(w, p.x, acc[4]); acc[5] = fmaf(w, p.y, acc[5]);
    p = __half22float2(*(__half2*)&v.w); acc[6] = fmaf(w, p.x, acc[6]); acc[7] = fmaf(w, p.y, acc[7]);
}
__device__ __forceinline__ void h8_scale(uint4 v, float s, float* acc) {
    float2 p;
    p = __half22float2(*(__half2*)&v.x); acc[0] = s * p.x; acc[1] = s * p.y;
    p = __half22float2(*(__half2*)&v.y); acc[2] = s * p.x; acc[3] = s * p.y;
    p = __half22float2(*(__half2*)&v.z); acc[4] = s * p.x; acc[5] = s * p.y;
    p = __half22float2(*(__half2*)&v.w); acc[6] = s * p.x; acc[7] = s * p.y;
}
__device__ __forceinline__ uint4 f8_to_h8(const float* f) {
    uint4 o;
    *(__half2*)&o.x = __floats2half2_rn(f[0], f[1]);
    *(__half2*)&o.y = __floats2half2_rn(f[2], f[3]);
    *(__half2*)&o.z = __floats2half2_rn(f[4], f[5]);
    *(__half2*)&o.w = __floats2half2_rn(f[6], f[7]);
    return o;
}

// ---------------- merged prep: dtype detect + cnt zero + x pad + weights + flat-x
#define XB   ((int)(XSZ / 256))                     // 11264 blocks
#define CVTB 7792
#define NNFEA ((long long)NN * FEA)
#define XPADB 10624                                 // (NNFEA + BATCH*8)/256
__global__ void k_prep(const void* __restrict__ ei, const float* __restrict__ x,
                       const float* __restrict__ W1, const float* __restrict__ W2,
                       const float* __restrict__ Wf0, const float* __restrict__ Wf1,
                       const float* __restrict__ Wf2,
                       int* __restrict__ cnt, __half* __restrict__ gh_base) {
    int blk = blockIdx.x;
    int t = threadIdx.x;
    if (blk < XB) {
        size_t idx = (size_t)blk * 256 + t;
        int i = (int)(idx >> 6), k = (int)(idx & 63);
        gh_base[OFF_XP + idx] = __float2half((k < FEA) ? x[(size_t)i * FEA + k] : 0.f);
        if (idx < NN) cnt[idx] = 0;
        if (idx == 0) {
            const long long* p = (const long long*)ei;
            int is32 = 0;
            for (int q = 0; q < 64; q++) {
                long long v = p[q];
                if (v < 0 || v >= NN) { is32 = 1; break; }
            }
            g_is32 = is32;
        }
        return;
    }
    blk -= XB;
    if (blk < CVTB) {
        int r = blk;
        float v; size_t off;
        __half* d;
        if (r < 64) {
            v = (r < FEA) ? W1[(size_t)r * 256 + t] : 0.f;
            d = gh_base + OFF_W1; off = (size_t)r * 256 + t;
        } else if (r < 320) {
            int k = r - 64;
            v = W2[(size_t)k * 256 + t];
            d = gh_base + OFF_W2; off = (size_t)k * 256 + t;
        } else if (r < 7280) {
            int k = r - 320;
            v = (k < MLP_IN) ? Wf0[(size_t)k * 256 + t] : 0.f;
            d = gh_base + OFF_F0; off = (size_t)k * 256 + t;
        } else if (r < 7536) {
            int k = r - 7280;
            v = Wf1[(size_t)k * 256 + t];
            d = gh_base + OFF_F1; off = (size_t)k * 256 + t;
        } else {
            int k = r - 7536;
            v = Wf2[(size_t)k * 256 + t];
            d = gh_base + OFF_F2; off = (size_t)k * 256 + t;
        }
        d[off] = __float2half(v);
        return;
    }
    blk -= CVTB;
    {
        __half* f = gh_base + OFF_F;
        long long idx = (long long)blk * 256 + t;
        if (idx < NNFEA) {
            int i = (int)(idx / FEA);
            int j = (int)(idx - (long long)i * FEA);
            int b = i / MACH, m = i - b * MACH;
            f[(size_t)b * KP0 + (size_t)m * (HID + FEA) + HID + j] = __float2half(x[idx]);
        } else {
            long long q = idx - NNFEA;
            int b = (int)(q >> 3), j = (int)(q & 7);
            f[(size_t)b * KP0 + MLP_IN + j] = __float2half(0.f);
        }
    }
}

__device__ __forceinline__ int edge_idx(const void* ei, int half, int e, int is32) {
    if (is32) return ((const int*)ei)[(size_t)half * EE + e];
    return (int)((const long long*)ei)[(size_t)half * EE + e];
}
__global__ void k_degfill(const void* __restrict__ ei, const float* __restrict__ ew,
                          int* __restrict__ cnt, int2* __restrict__ srcw) {
    int e = blockIdx.x * 256 + threadIdx.x;
    if (e >= EE) return;
    int is32 = g_is32;
    int r = edge_idx(ei, 0, e, is32);
    int c = edge_idx(ei, 1, e, is32);
    if ((unsigned)r >= (unsigned)NN || (unsigned)c >= (unsigned)NN) return;
    float w = ew[e];
    int p = atomicAdd(&cnt[c], 1);
    if (p < CAP) srcw[(size_t)c * CAP + p] = make_int2(r, __float_as_int(w));
}
__global__ void k_dinv(const int2* __restrict__ srcw, const int* __restrict__ cnt,
                       float* __restrict__ dinv) {
    int node = (blockIdx.x * 256 + threadIdx.x) >> 5;
    int lane = threadIdx.x & 31;
    if (node >= NN) return;
    int c = cnt[node]; if (c > CAP) c = CAP;
    float s = 0.f;
    for (int e = lane; e < c; e += 32) s += __int_as_float(srcw[(size_t)node * CAP + e].y);
#pragma unroll
    for (int o = 16; o; o >>= 1) s += __shfl_xor_sync(0xffffffffu, s, o);
    if (lane == 0) dinv[node] = rsqrtf(s + 1.0f);
}

// ---------------- gather x (fp16 uint4, 8 lanes/node, 4-wide batched) --------
__global__ __launch_bounds__(256)
void k_gather_x(const uint4* __restrict__ xp4, const float* __restrict__ dinv,
                const int* __restrict__ cnt, const int2* __restrict__ srcw,
                uint4* __restrict__ xq4) {
    int sub = threadIdx.x >> 3, lane = threadIdx.x & 7;
    int i = blockIdx.x * 32 + sub;
    __shared__ int   ssrc[32][CAP];
    __shared__ float snrm[32][CAP];
    int c = cnt[i]; if (c > CAP) c = CAP;
    float di = dinv[i];
    for (int e = lane; e < c; e += 8) {
        int2 sv = srcw[(size_t)i * CAP + e];
        ssrc[sub][e] = sv.x * 8;
        snrm[sub][e] = dinv[sv.x] * __int_as_float(sv.y) * di;
    }
    __syncwarp();

    float acc[8];
    h8_scale(xp4[i * 8 + lane], di * di, acc);
    int e = 0;
    for (; e + 4 <= c; e += 4) {
        uint4 v0 = xp4[ssrc[sub][e]     + lane];
        uint4 v1 = xp4[ssrc[sub][e + 1] + lane];
        uint4 v2 = xp4[ssrc[sub][e + 2] + lane];
        uint4 v3 = xp4[ssrc[sub][e + 3] + lane];
        h8_acc(v0, snrm[sub][e],     acc);
        h8_acc(v1, snrm[sub][e + 1], acc);
        h8_acc(v2, snrm[sub][e + 2], acc);
        h8_acc(v3, snrm[sub][e + 3], acc);
    }
    for (; e < c; e++)
        h8_acc(xp4[ssrc[sub][e] + lane], snrm[sub][e], acc);
    xq4[i * 8 + lane] = f8_to_h8(acc);
}

// ---------------- gather h (fp16 uint4, 1 warp/node, 4-wide batched) ---------
__global__ __launch_bounds__(256)
void k_gather_h(const uint4* __restrict__ h4,
                const float* __restrict__ dinv, const int* __restrict__ cnt,
                const int2* __restrict__ srcw, uint4* __restrict__ a4) {
    int sub = threadIdx.x >> 5, lane = threadIdx.x & 31;
    int i = blockIdx.x * 8 + sub;
    __shared__ int   ssrc[8][CAP];
    __shared__ float snrm[8][CAP];
    int c = cnt[i]; if (c > CAP) c = CAP;
    float di = dinv[i];
    for (int e = lane; e < c; e += 32) {
        int2 sv = srcw[(size_t)i * CAP + e];
        ssrc[sub][e] = sv.x * 32;
        snrm[sub][e] = dinv[sv.x] * __int_as_float(sv.y) * di;
    }
    __syncwarp();

    float acc[8];
    h8_scale(h4[i * 32 + lane], di * di, acc);
    int e = 0;
    for (; e + 4 <= c; e += 4) {
        uint4 v0 = h4[ssrc[sub][e]     + lane];
        uint4 v1 = h4[ssrc[sub][e + 1] + lane];
        uint4 v2 = h4[ssrc[sub][e + 2] + lane];
        uint4 v3 = h4[ssrc[sub][e + 3] + lane];
        h8_acc(v0, snrm[sub][e],     acc);
        h8_acc(v1, snrm[sub][e + 1], acc);
        h8_acc(v2, snrm[sub][e + 2], acc);
        h8_acc(v3, snrm[sub][e + 3], acc);
    }
    for (; e < c; e++)
        h8_acc(h4[ssrc[sub][e] + lane], snrm[sub][e], acc);
    a4[i * 32 + lane] = f8_to_h8(acc);
}

// ---------------- fp16 tensor-core GEMM (cp.async double-buffered) -----------
// MODE 0: fp32 partial store to C + blockIdx.z*ZSZ (split-K)
// MODE 1: bias + leaky + fp16 store, linear stride 256 (conv1 -> h)
// MODE 2: bias + leaky + fp16 store, flat-mapped (conv2 -> flat)
template<int MODE>
__global__ __launch_bounds__(256)
void bmma(const __half* __restrict__ A, const __half* __restrict__ B,
          float* __restrict__ C, const float* __restrict__ bias,
          __half* __restrict__ o, int K, int kstep) {
    __shared__ __align__(16) __half As[2][128][24];
    __shared__ __align__(16) __half Bs[2][16][136];
    constexpr u32 ABUF = 128 * 24 * 2;
    constexpr u32 BBUF = 16 * 136 * 2;

    const int tid = threadIdx.x;
    const int lane = tid & 31, warp = tid >> 5;
    const int wm = warp >> 2, wn = warp & 3;
    const int row0 = blockIdx.y * 128, col0 = blockIdx.x * 128;
    const int kb = blockIdx.z * kstep;
    const int ke = min(kb + kstep, K);

    const int ar = tid >> 1, ac = (tid & 1) * 8;
    const int bkr = tid >> 4, bc = (tid & 15) * 8;
    const size_t a_base = (size_t)(row0 + ar) * K + ac;

    const u32 a_dst = smem_u32(&As[0][ar][ac]);
    const u32 b_dst = smem_u32(&Bs[0][bkr][bc]);

    float acc[4][4][4];
#pragma unroll
    for (int i = 0; i < 4; i++)
#pragma unroll
        for (int j = 0; j < 4; j++)
#pragma unroll
            for (int q = 0; q < 4; q++) acc[i][j][q] = 0.f;

    const int lr = (lane & 7) + ((lane >> 3) & 1) * 8;
    const int lc = (lane >> 4) * 8;
    u32 aaddr[4], baddr[2];
#pragma unroll
    for (int mf = 0; mf < 4; mf++)
        aaddr[mf] = smem_u32(&As[0][wm * 64 + mf * 16 + lr][lc]);
#pragma unroll
    for (int g = 0; g < 2; g++)
        baddr[g] = smem_u32(&Bs[0][lr][wn * 32 + g * 16 + lc]);

    auto load_stage = [&](int buf, int k0) {
        if (k0 < ke) {
            cp16(a_dst + buf * ABUF, A + a_base + k0);
            cp16(b_dst + buf * BBUF, B + (size_t)(k0 + bkr) * 256 + col0 + bc);
        }
        asm volatile("cp.async.commit_group;");
    };

    load_stage(0, kb);
    load_stage(1, kb + 16);

    int buf = 0;
    for (int k0 = kb; k0 < ke; k0 += 16, buf ^= 1) {
        asm volatile("cp.async.wait_group 1;");
        __syncthreads();

        u32 a[4][4], b[4][2];
#pragma unroll
        for (int mf = 0; mf < 4; mf++)
            ldsm_x4(a[mf], aaddr[mf] + buf * ABUF);
#pragma unroll
        for (int g = 0; g < 2; g++) {
            u32 t[4];
            ldsm_x4_t(t, baddr[g] + buf * BBUF);
            b[2*g][0] = t[0]; b[2*g][1] = t[1];
            b[2*g+1][0] = t[2]; b[2*g+1][1] = t[3];
        }
#pragma unroll
        for (int mf = 0; mf < 4; mf++)
#pragma unroll
            for (int nf = 0; nf < 4; nf++)
                mmaf16(acc[mf][nf], a[mf], b[nf]);
        __syncthreads();
        load_stage(buf, k0 + 32);
    }

    const int er = lane >> 2, ec = (lane & 3) * 2;
    float* Cz = (MODE == 0) ? C + (size_t)blockIdx.z * ZSZ : C;
#pragma unroll
    for (int mf = 0; mf < 4; mf++)
#pragma unroll
        for (int nf = 0; nf < 4; nf++) {
            int r = row0 + wm * 64 + mf * 16 + er;
            int c = col0 + wn * 32 + nf * 8 + ec;
            if (MODE == 0) {
                float* p0 = &Cz[(size_t)r * 256 + c];
                float* p1 = &Cz[(size_t)(r + 8) * 256 + c];
                p0[0] = acc[mf][nf][0]; p0[1] = acc[mf][nf][1];
                p1[0] = acc[mf][nf][2]; p1[1] = acc[mf][nf][3];
            } else {
                float bv0 = bias[c], bv1 = bias[c + 1];
#pragma unroll
                for (int half = 0; half < 2; half++) {
                    int rr = r + half * 8;
                    float v0 = acc[mf][nf][half * 2]     + bv0;
                    float v1 = acc[mf][nf][half * 2 + 1] + bv1;
                    v0 = v0 > 0.f ? v0 : NEG_SLOPE * v0;
                    v1 = v1 > 0.f ? v1 : NEG_SLOPE * v1;
                    size_t p;
                    if (MODE == 1) {
                        p = (size_t)rr * 256 + c;
                    } else {
                        int b = rr / MACH, m = rr - b * MACH;
                        p = (size_t)b * KP0 + (size_t)m * (HID + FEA) + c;
                    }
                    *(__half2*)&o[p] = __floats2half2_rn(v0, v1);
                }
            }
        }
}

// ---------------- split-K reduce + bias + leaky + fp16 store (float4 loads) --
template<int S>
__global__ void k_epi(const float* __restrict__ zp, const float* __restrict__ bias,
                      __half* __restrict__ z) {
    size_t i4 = (size_t)blockIdx.x * 256 + threadIdx.x;   // index in float4 units
    int cbase = (int)((i4 & 63) << 2);
    float4 v = *(const float4*)&zp[i4 * 4];
#pragma unroll
    for (int s = 1; s < S; s++) {
        float4 u = *(const float4*)&zp[s * ZSZ + i4 * 4];
        v.x += u.x; v.y += u.y; v.z += u.z; v.w += u.w;
    }
    v.x += bias[cbase + 0]; v.y += bias[cbase + 1];
    v.z += bias[cbase + 2]; v.w += bias[cbase + 3];
    v.x = v.x > 0.f ? v.x : NEG_SLOPE * v.x;
    v.y = v.y > 0.f ? v.y : NEG_SLOPE * v.y;
    v.z = v.z > 0.f ? v.z : NEG_SLOPE * v.z;
    v.w = v.w > 0.f ? v.w : NEG_SLOPE * v.w;
    uint2 o;
    *(__half2*)&o.x = __floats2half2_rn(v.x, v.y);
    *(__half2*)&o.y = __floats2half2_rn(v.z, v.w);
    *(uint2*)&z[i4 * 4] = o;
}

// ---------------- final: reduce + bias + leaky + head GEMV -------------------
__global__ __launch_bounds__(256)
void k_epihead(const float* __restrict__ zp, const float* __restrict__ bias,
               const float* __restrict__ Wo, const float* __restrict__ bo,
               float* __restrict__ out) {
    __shared__ float zrow[HID];
    int b = blockIdx.x, t = threadIdx.x;
    size_t i = (size_t)b * HID + t;
    float v = bias[t];
#pragma unroll
    for (int s = 0; s < 4; s++) v += zp[s * ZSZ + i];
    v = v > 0.f ? v : NEG_SLOPE * v;
    zrow[t] = v;
    __syncthreads();
    if (t < 128) {
        int j = t >> 5, lane = t & 31;
        float a = 0.f;
#pragma unroll
        for (int q = 0; q < 8; q++) {
            int k = lane + q * 32;
            a = fmaf(zrow[k], Wo[k * 4 + j], a);
        }
#pragma unroll
        for (int o = 16; o > 0; o >>= 1)
            a += __shfl_down_sync(0xffffffffu, a, o);
        if (lane == 0) out[(size_t)b * 4 + j] = a + bo[j];
    }
}

// ---------------- launcher ---------------------------------------------------
extern "C" void kernel_launch(void* const* d_in, const int* in_sizes, int n_in,
                              void* d_out, int out_size) {
    const float* x   = (const float*)d_in[0];
    const void*  ei  = d_in[1];
    const float* ew  = (const float*)d_in[2];
    const float* W1  = (const float*)d_in[3];
    const float* b1  = (const float*)d_in[4];
    const float* W2  = (const float*)d_in[5];
    const float* b2  = (const float*)d_in[6];
    const float* Wf0 = (const float*)d_in[7];
    const float* bf0 = (const float*)d_in[8];
    const float* Wf1 = (const float*)d_in[9];
    const float* bf1 = (const float*)d_in[10];
    const float* Wf2 = (const float*)d_in[11];
    const float* bf2 = (const float*)d_in[12];
    const float* Wo  = (const float*)d_in[13];
    const float* bo  = (const float*)d_in[14];
    float* out = (float*)d_out;

    float* gf = nullptr; int* gcnt = nullptr; int2* gsw = nullptr; __half* gh = nullptr;
    cudaGetSymbolAddress((void**)&gf, g_f);
    cudaGetSymbolAddress((void**)&gcnt, g_cnt);
    cudaGetSymbolAddress((void**)&gsw, g_srcw);
    cudaGetSymbolAddress((void**)&gh, g_h);

    float* dinv = gf + OFF_DINV;
    float* zp   = gf + OFF_ZP;

    __half *xp = gh + OFF_XP, *xq = gh + OFF_XQ;
    __half *h  = gh + OFF_H,  *a  = gh + OFF_A;
    __half *f  = gh + OFF_F;
    __half *w1 = gh + OFF_W1, *w2 = gh + OFF_W2;
    __half *f0 = gh + OFF_F0, *f1 = gh + OFF_F1, *f2 = gh + OFF_F2;
    __half *z  = gh + OFF_Z;

    const int NB_E = (EE + 255) / 256;

    // merged prep (x pad + cnt zero + dtype detect + weight cvt + flat-x)
    k_prep<<<XB + CVTB + XPADB, 256>>>(ei, x, W1, W2, Wf0, Wf1, Wf2, gcnt, gh);  // 1
    k_degfill<<<NB_E, 256>>>(ei, ew, gcnt, gsw);                                 // 2
    k_dinv<<<NN / 8, 256>>>(gsw, gcnt, dinv);                                    // 3
    k_gather_x<<<NN / 32, 256>>>((const uint4*)xp, dinv, gcnt, gsw,
                                 (uint4*)xq);                                    // 4 <- profiled

    // conv1
    bmma<1><<<dim3(2, NN / 128, 1), 256>>>(xq, w1, nullptr, b1, h, KP1, KP1);

    // conv2
    k_gather_h<<<NN / 8, 256>>>((const uint4*)h, dinv, gcnt, gsw, (uint4*)a);
    bmma<2><<<dim3(2, NN / 128, 1), 256>>>(a, w2, nullptr, b2, f, HID, HID);

    // MLP0: split-K=8 -> partials -> reduce epi (float4)
    bmma<0><<<dim3(2, BATCH / 128, 8), 256>>>(f, f0, zp, nullptr, nullptr, KP0, 880);
    k_epi<8><<<(int)(ZSZ / 1024), 256>>>(zp, bf0, z);

    // MLP1: split-K=4
    bmma<0><<<dim3(2, BATCH / 128, 4), 256>>>(z, f1, zp, nullptr, nullptr, HID, 64);
    k_epi<4><<<(int)(ZSZ / 1024), 256>>>(zp, bf1, z);

    // MLP2: split-K=4 -> fused reduce + head
    bmma<0><<<dim3(2, BATCH / 128, 4), 256>>>(z, f2, zp, nullptr, nullptr, HID, 64);
    k_epihead<<<BATCH, 256>>>(zp, bf2, Wo, bo, out);
}